// round 12
// baseline (speedup 1.0000x reference)
#include <cuda_runtime.h>
#include <cuda_fp16.h>
#include <cstdint>
#include <cstddef>

#define T_LEN 16384
#define L_LAB 1024
#define LOG2E 1.4426950408889634f
#define LN2_D 0.6931471805599453
#define CSIZE 16           // cluster size (16 SMs do all the work)
#define TPB   1024
#define ROWS_PER_BLK 64    // L_LAB / CSIZE

// ---- persistent scratch (no allocations allowed) ----
__device__ float  g_alpha[L_LAB];
__device__ double g_csum;
__device__ double g_gold;

static __device__ __forceinline__ float ex2f(float x) {
    float r; asm("ex2.approx.ftz.f32 %0, %1;" : "=f"(r) : "f"(x)); return r;
}
static __device__ __forceinline__ float lg2f_(float x) {
    float r; asm("lg2.approx.f32 %0, %1;" : "=f"(r) : "f"(x)); return r;
}
static __device__ __forceinline__ unsigned smem_u32(const void* p) {
    unsigned a;
    asm("{ .reg .u64 t; cvta.to.shared.u64 t, %1; cvt.u32.u64 %0, t; }"
        : "=r"(a) : "l"(p));
    return a;
}
static __device__ __forceinline__ void st_dsmem64(unsigned localAddr, unsigned peer,
                                                  unsigned long long v) {
    unsigned r;
    asm volatile("mapa.shared::cluster.u32 %0, %1, %2;" : "=r"(r) : "r"(localAddr), "r"(peer));
    asm volatile("st.shared::cluster.b64 [%0], %1;" :: "r"(r), "l"(v) : "memory");
}
static __device__ __forceinline__ void st_dsmem32(unsigned localAddr, unsigned peer, float v) {
    unsigned r;
    asm volatile("mapa.shared::cluster.u32 %0, %1, %2;" : "=r"(r) : "r"(localAddr), "r"(peer));
    asm volatile("st.shared::cluster.b32 [%0], %1;" :: "r"(r), "f"(v) : "memory");
}
#define CLUSTER_SYNC() do { \
    asm volatile("barrier.cluster.arrive.aligned;" ::: "memory"); \
    asm volatile("barrier.cluster.wait.aligned;"   ::: "memory"); \
} while (0)

// Grid (16, 2), cluster (16,1,1):
//   y==0: the compute cluster (one CTA per SM, 1024 threads).
//   y==1, x==0: gold-path score; other y==1 blocks exit (their cluster never syncs).
__global__ void __launch_bounds__(TPB, 1) __cluster_dims__(CSIZE, 1, 1)
crf_main(const float* __restrict__ pred,
         const int*   __restrict__ ref,
         const float* __restrict__ trans)
{
    if (blockIdx.y == 1) {
        if (blockIdx.x != 0) return;
        __shared__ double red[TPB];
        int tid = threadIdx.x;
        double g = 0.0;
        for (int t = tid; t < T_LEN; t += TPB) {
            int r = __ldg(&ref[t]);
            int p = (t == 0) ? (L_LAB - 2) : __ldg(&ref[t - 1]);
            g += (double)__ldg(&pred[(size_t)t * L_LAB + r])
               + (double)__ldg(&trans[(size_t)r * L_LAB + p]);
        }
        red[tid] = g; __syncthreads();
        for (int s = TPB / 2; s > 0; s >>= 1) {
            if (tid < s) red[tid] += red[tid + s];
            __syncthreads();
        }
        if (tid == 0)
            g_gold = red[0] + (double)__ldg(&trans[(size_t)(L_LAB - 1) * L_LAB + __ldg(&ref[T_LEN - 1])]);
        return;
    }

    // ================= compute cluster =================
    __shared__ __align__(16) float  sAlpha[2][L_LAB];   // exchanged alphas (parity)
    __shared__ __align__(16) __half sEh[L_LAB];         // e[i] = 2^(alpha[i]-m)
    __shared__ __align__(8)  float  sOut[ROWS_PER_BLK];
    __shared__ __align__(16) float  sPart[256];         // [g:8][row:8][c:4] slice partials
    __shared__ float sMaxArr[2][CSIZE];                 // chunk maxima (parity)

    const int tid = threadIdx.x;
    const int w = tid >> 5, l = tid & 31;
    const int g = w >> 2, c = w & 3;                    // row-group / label-slice
    const unsigned rank = blockIdx.x;
    const int rowBase = (int)rank * ROWS_PER_BLK + g * 8;

    // ---- precompute expW = exp(W), 8 rows x 8 labels per thread, packed fp16.
    // Thread (g,c,l): rows rowBase..rowBase+7, labels c*256 + 8l .. +7.
    __half2 hW[32];
    #pragma unroll
    for (int r = 0; r < 8; ++r) {
        const float* tr = trans + (size_t)(rowBase + r) * L_LAB + c * 256 + 8 * l;
        float4 u = *reinterpret_cast<const float4*>(tr);
        float4 v = *reinterpret_cast<const float4*>(tr + 4);
        hW[r * 4 + 0] = __floats2half2_rn(ex2f(u.x * LOG2E), ex2f(u.y * LOG2E));
        hW[r * 4 + 1] = __floats2half2_rn(ex2f(u.z * LOG2E), ex2f(u.w * LOG2E));
        hW[r * 4 + 2] = __floats2half2_rn(ex2f(v.x * LOG2E), ex2f(v.y * LOG2E));
        hW[r * 4 + 3] = __floats2half2_rn(ex2f(v.z * LOG2E), ex2f(v.w * LOG2E));
    }

    // ---- step 1 closed form: alpha2(1)[j] = (W[j,START] + pred[0,j]) * log2e
    float fcur = 0.f, fnext = 0.f;     // feats for rows owned by tid<64
    if (tid < ROWS_PER_BLK) {
        int j = (int)rank * ROWS_PER_BLK + tid;
        float ws = __ldg(&trans[(size_t)j * L_LAB + (L_LAB - 2)]);
        sOut[tid] = (ws + __ldg(&pred[j])) * LOG2E;
        fcur = __ldg(&pred[(size_t)L_LAB + j]);
    }
    __syncthreads();
    if (w < CSIZE) {                   // warp p pushes the 64-value chunk to peer p
        float2 f = *reinterpret_cast<float2*>(&sOut[2 * l]);
        unsigned long long v;
        asm("mov.b64 %0, {%1,%2};" : "=l"(v) : "f"(f.x), "f"(f.y));
        st_dsmem64(smem_u32(&sAlpha[1][rank * ROWS_PER_BLK + 2 * l]), (unsigned)w, v);
    } else if (w == CSIZE) {           // warp 16: chunk max -> all peers
        float mm = fmaxf(sOut[l], sOut[l + 32]);
        #pragma unroll
        for (int o = 16; o > 0; o >>= 1) mm = fmaxf(mm, __shfl_xor_sync(0xffffffffu, mm, o));
        mm = __shfl_sync(0xffffffffu, mm, 0);
        if (l < CSIZE)
            st_dsmem32(smem_u32(&sMaxArr[1][rank]), (unsigned)l, mm);
    }
    CLUSTER_SYNC();

    double csum = 0.0;

    for (int t = 1; t < T_LEN; ++t) {
        const int buf = t & 1, nbuf = buf ^ 1;

        // ---- global max from 16 pushed chunk maxima (exact -> deterministic).
        // Broadcast LDS + fmax tree; no barriers, no shuffles.
        const float* ma = sMaxArr[buf];
        float m = fmaxf(fmaxf(fmaxf(ma[0], ma[1]),  fmaxf(ma[2], ma[3])),
                        fmaxf(fmaxf(ma[4], ma[5]),  fmaxf(ma[6], ma[7])));
        m = fmaxf(m, fmaxf(fmaxf(fmaxf(ma[8], ma[9]),   fmaxf(ma[10], ma[11])),
                           fmaxf(fmaxf(ma[12], ma[13]), fmaxf(ma[14], ma[15]))));
        if (rank == 0 && tid == 0) csum += (double)m;

        // e[i] = 2^(alpha[i]-m) <= 1: fp16-safe
        float a = sAlpha[buf][tid];
        sEh[tid] = __float2half_rn(ex2f(a - m));
        __syncthreads();

        if (tid < ROWS_PER_BLK && t + 1 < T_LEN)
            fnext = __ldg(&pred[(size_t)(t + 1) * L_LAB + rank * ROWS_PER_BLK + tid]);

        // ---- inner: 8 rows x 8 labels per thread; one 16B e-load per thread ----
        uint4 raw = *reinterpret_cast<const uint4*>(&sEh[c * 256 + 8 * l]);
        __half2 e0 = *reinterpret_cast<__half2*>(&raw.x);
        __half2 e1 = *reinterpret_cast<__half2*>(&raw.y);
        __half2 e2 = *reinterpret_cast<__half2*>(&raw.z);
        __half2 e3 = *reinterpret_cast<__half2*>(&raw.w);
        float p[8];
        #pragma unroll
        for (int r = 0; r < 8; ++r) {
            __half2 h = __hmul2(e0, hW[r * 4 + 0]);
            h = __hfma2(e1, hW[r * 4 + 1], h);
            h = __hfma2(e2, hW[r * 4 + 2], h);
            h = __hfma2(e3, hW[r * 4 + 3], h);
            float2 f2 = __half22float2(h);
            p[r] = f2.x + f2.y;
        }

        // ---- multi-value butterfly: fold 8 row-partials across 32 lanes.
        // After stages, lane l holds the full 32-lane sum for row (l>>2)&7.
        const bool hi16 = (l & 16), hi8 = (l & 8), hi4 = (l & 4);
        float q0, q1, q2, q3, u0, u1, v;
        {
            float s, tt;
            s = hi16 ? p[0] : p[4]; tt = __shfl_xor_sync(0xffffffffu, s, 16);
            q0 = (hi16 ? p[4] : p[0]) + tt;
            s = hi16 ? p[1] : p[5]; tt = __shfl_xor_sync(0xffffffffu, s, 16);
            q1 = (hi16 ? p[5] : p[1]) + tt;
            s = hi16 ? p[2] : p[6]; tt = __shfl_xor_sync(0xffffffffu, s, 16);
            q2 = (hi16 ? p[6] : p[2]) + tt;
            s = hi16 ? p[3] : p[7]; tt = __shfl_xor_sync(0xffffffffu, s, 16);
            q3 = (hi16 ? p[7] : p[3]) + tt;

            s = hi8 ? q0 : q2; tt = __shfl_xor_sync(0xffffffffu, s, 8);
            u0 = (hi8 ? q2 : q0) + tt;
            s = hi8 ? q1 : q3; tt = __shfl_xor_sync(0xffffffffu, s, 8);
            u1 = (hi8 ? q3 : q1) + tt;

            s = hi4 ? u0 : u1; tt = __shfl_xor_sync(0xffffffffu, s, 4);
            v = (hi4 ? u1 : u0) + tt;
            v += __shfl_xor_sync(0xffffffffu, v, 2);
            v += __shfl_xor_sync(0xffffffffu, v, 1);
        }
        if ((l & 3) == 0) {
            int row = l >> 2;                       // lane-bit folding => row = l/4
            sPart[g * 32 + row * 4 + c] = v;        // [g][row][c]
        }
        __syncthreads();

        // ---- combine 4 slice-partials per row; lg2 + feat; write sOut ----
        if (tid < ROWS_PER_BLK) {
            float4 s4 = *reinterpret_cast<const float4*>(&sPart[tid * 4]);
            float s = (s4.x + s4.y) + (s4.z + s4.w);
            sOut[tid] = lg2f_(s) + fcur * LOG2E;
            fcur = fnext;
        }
        __syncthreads();

        // ---- push data (warps 0..15) + chunk max (warp 16) to all peers ----
        if (w < CSIZE) {
            float2 f = *reinterpret_cast<float2*>(&sOut[2 * l]);
            unsigned long long vv;
            asm("mov.b64 %0, {%1,%2};" : "=l"(vv) : "f"(f.x), "f"(f.y));
            st_dsmem64(smem_u32(&sAlpha[nbuf][rank * ROWS_PER_BLK + 2 * l]), (unsigned)w, vv);
        } else if (w == CSIZE) {
            float mm = fmaxf(sOut[l], sOut[l + 32]);
            #pragma unroll
            for (int o = 16; o > 0; o >>= 1) mm = fmaxf(mm, __shfl_xor_sync(0xffffffffu, mm, o));
            mm = __shfl_sync(0xffffffffu, mm, 0);
            if (l < CSIZE)
                st_dsmem32(smem_u32(&sMaxArr[nbuf][rank]), (unsigned)l, mm);
        }
        CLUSTER_SYNC();                // orders DSMEM stores; doubles as block barrier
    }

    // alpha(T_LEN) sits in parity buffer (T_LEN & 1) == 0
    if (rank == 0) {
        g_alpha[tid] = sAlpha[0][tid];
        if (tid == 0) g_csum = csum;
    }
}

// Terminal: forward = LSE_j(alpha2(T)[j] + W2[STOP,j]) + csum, max-stabilized
// (the STOP row is uniformly -1e4; without the max everything underflows).
__global__ void crf_final(const float* __restrict__ trans, float* __restrict__ out)
{
    __shared__ float  sm[256];
    __shared__ double sd[256];
    int tid = threadIdx.x;

    float x[4];
    float m = -3.4e38f;
    #pragma unroll
    for (int q = 0; q < 4; ++q) {
        int jj = q * 256 + tid;
        float a  = g_alpha[jj];
        float wl = __ldg(&trans[(size_t)(L_LAB - 1) * L_LAB + jj]) * LOG2E;
        x[q] = a + wl;
        m = fmaxf(m, x[q]);
    }
    sm[tid] = m; __syncthreads();
    for (int s = 128; s > 0; s >>= 1) {
        if (tid < s) sm[tid] = fmaxf(sm[tid], sm[tid + s]);
        __syncthreads();
    }
    float M = sm[0];

    double loc = 0.0;
    #pragma unroll
    for (int q = 0; q < 4; ++q) loc += (double)ex2f(x[q] - M);
    sd[tid] = loc; __syncthreads();
    for (int s = 128; s > 0; s >>= 1) {
        if (tid < s) sd[tid] += sd[tid + s];
        __syncthreads();
    }
    if (tid == 0) {
        double fwd = (log2(sd[0]) + (double)M + g_csum) * LN2_D;
        out[0] = (float)(fwd - g_gold);
    }
}

extern "C" void kernel_launch(void* const* d_in, const int* in_sizes, int n_in,
                              void* d_out, int out_size)
{
    const float* pred = nullptr;
    const int*   ref  = nullptr;
    const float* trans = nullptr;
    for (int i = 0; i < n_in; ++i) {
        if (in_sizes[i] == T_LEN)                 ref   = (const int*)d_in[i];
        else if (in_sizes[i] == L_LAB * L_LAB)    trans = (const float*)d_in[i];
        else if (in_sizes[i] == T_LEN * L_LAB)    pred  = (const float*)d_in[i];
    }
    cudaFuncSetAttribute(crf_main, cudaFuncAttributeNonPortableClusterSizeAllowed, 1);

    dim3 grid(CSIZE, 2);
    crf_main<<<grid, TPB>>>(pred, ref, trans);
    crf_final<<<1, 256>>>(trans, (float*)d_out);
}

// round 13
// speedup vs baseline: 1.1565x; 1.1565x over previous
#include <cuda_runtime.h>
#include <cuda_fp16.h>
#include <cstdint>
#include <cstddef>

#define T_LEN 16384
#define L_LAB 1024
#define LOG2E 1.4426950408889634f
#define LN2_D 0.6931471805599453
#define CSIZE 16           // cluster size (16 SMs do all the work)
#define TPB   1024
#define ROWS_PER_BLK 64    // L_LAB / CSIZE

// ---- persistent scratch (no allocations allowed) ----
__device__ float  g_alpha[L_LAB];
__device__ double g_csum;
__device__ double g_gold;

static __device__ __forceinline__ float ex2f(float x) {
    float r; asm("ex2.approx.ftz.f32 %0, %1;" : "=f"(r) : "f"(x)); return r;
}
static __device__ __forceinline__ float lg2f_(float x) {
    float r; asm("lg2.approx.f32 %0, %1;" : "=f"(r) : "f"(x)); return r;
}
static __device__ __forceinline__ unsigned smem_u32(const void* p) {
    unsigned a;
    asm("{ .reg .u64 t; cvta.to.shared.u64 t, %1; cvt.u32.u64 %0, t; }"
        : "=r"(a) : "l"(p));
    return a;
}
static __device__ __forceinline__ void st_dsmem64(unsigned localAddr, unsigned peer,
                                                  unsigned long long v) {
    unsigned r;
    asm volatile("mapa.shared::cluster.u32 %0, %1, %2;" : "=r"(r) : "r"(localAddr), "r"(peer));
    asm volatile("st.shared::cluster.b64 [%0], %1;" :: "r"(r), "l"(v) : "memory");
}
static __device__ __forceinline__ void st_dsmem32(unsigned localAddr, unsigned peer, float v) {
    unsigned r;
    asm volatile("mapa.shared::cluster.u32 %0, %1, %2;" : "=r"(r) : "r"(localAddr), "r"(peer));
    asm volatile("st.shared::cluster.b32 [%0], %1;" :: "r"(r), "f"(v) : "memory");
}
#define CLUSTER_SYNC() do { \
    asm volatile("barrier.cluster.arrive.aligned;" ::: "memory"); \
    asm volatile("barrier.cluster.wait.aligned;"   ::: "memory"); \
} while (0)

// Grid (16, 2), cluster (16,1,1):
//   y==0: the compute cluster (one CTA per SM, 1024 threads).
//   y==1, x==0: gold-path score; other y==1 blocks exit (their cluster never syncs).
__global__ void __launch_bounds__(TPB, 1) __cluster_dims__(CSIZE, 1, 1)
crf_main(const float* __restrict__ pred,
         const int*   __restrict__ ref,
         const float* __restrict__ trans)
{
    if (blockIdx.y == 1) {
        if (blockIdx.x != 0) return;
        __shared__ double red[TPB];
        int tid = threadIdx.x;
        double g = 0.0;
        for (int t = tid; t < T_LEN; t += TPB) {
            int r = __ldg(&ref[t]);
            int p = (t == 0) ? (L_LAB - 2) : __ldg(&ref[t - 1]);
            g += (double)__ldg(&pred[(size_t)t * L_LAB + r])
               + (double)__ldg(&trans[(size_t)r * L_LAB + p]);
        }
        red[tid] = g; __syncthreads();
        for (int s = TPB / 2; s > 0; s >>= 1) {
            if (tid < s) red[tid] += red[tid + s];
            __syncthreads();
        }
        if (tid == 0)
            g_gold = red[0] + (double)__ldg(&trans[(size_t)(L_LAB - 1) * L_LAB + __ldg(&ref[T_LEN - 1])]);
        return;
    }

    // ================= compute cluster (R10 tiling: 2 rows/warp) =================
    __shared__ __align__(16) float  sAlpha[2][L_LAB];  // exchanged alphas (parity)
    __shared__ __align__(16) __half sEh[L_LAB];        // e[i] = 2^(alpha[i]-m), fp16
    __shared__ __align__(8)  float  sOut[ROWS_PER_BLK];
    __shared__ float sMaxArr[2][CSIZE];                // pushed chunk maxima (parity)

    const int tid = threadIdx.x;
    const int w = tid >> 5, l = tid & 31;
    const unsigned rank = blockIdx.x;
    const int jA = (int)rank * ROWS_PER_BLK + 2 * w;   // warp's rows: jA, jA+1

    // ---- precompute expW = exp(W) for rows jA, jA+1, packed fp16.
    // Thread (w,l), chunk k2=0..3 covers labels i = k2*256 + 8l + m, m=0..7.
    __half2 hA[16], hB[16];
    {
        const float* ta = trans + (size_t)jA * L_LAB;
        const float* tb = ta + L_LAB;
        #pragma unroll
        for (int k2 = 0; k2 < 4; ++k2) {
            float4 u = *reinterpret_cast<const float4*>(ta + k2 * 256 + 8 * l);
            float4 v = *reinterpret_cast<const float4*>(ta + k2 * 256 + 8 * l + 4);
            hA[k2 * 4 + 0] = __floats2half2_rn(ex2f(u.x * LOG2E), ex2f(u.y * LOG2E));
            hA[k2 * 4 + 1] = __floats2half2_rn(ex2f(u.z * LOG2E), ex2f(u.w * LOG2E));
            hA[k2 * 4 + 2] = __floats2half2_rn(ex2f(v.x * LOG2E), ex2f(v.y * LOG2E));
            hA[k2 * 4 + 3] = __floats2half2_rn(ex2f(v.z * LOG2E), ex2f(v.w * LOG2E));
            u = *reinterpret_cast<const float4*>(tb + k2 * 256 + 8 * l);
            v = *reinterpret_cast<const float4*>(tb + k2 * 256 + 8 * l + 4);
            hB[k2 * 4 + 0] = __floats2half2_rn(ex2f(u.x * LOG2E), ex2f(u.y * LOG2E));
            hB[k2 * 4 + 1] = __floats2half2_rn(ex2f(u.z * LOG2E), ex2f(u.w * LOG2E));
            hB[k2 * 4 + 2] = __floats2half2_rn(ex2f(v.x * LOG2E), ex2f(v.y * LOG2E));
            hB[k2 * 4 + 3] = __floats2half2_rn(ex2f(v.z * LOG2E), ex2f(v.w * LOG2E));
        }
    }

    // ---- step 1 closed form: alpha2(1)[j] = (W[j,START] + pred[0,j]) * log2e
    float2 fcur, fnext;               // feats (lane 0 only)
    if (l == 0) {
        float wsA = __ldg(&trans[(size_t)jA * L_LAB + (L_LAB - 2)]);
        float wsB = __ldg(&trans[(size_t)(jA + 1) * L_LAB + (L_LAB - 2)]);
        float2 p0 = __ldg(reinterpret_cast<const float2*>(pred + jA));
        sOut[2 * w]     = (wsA + p0.x) * LOG2E;
        sOut[2 * w + 1] = (wsB + p0.y) * LOG2E;
        fcur = __ldg(reinterpret_cast<const float2*>(pred + (size_t)L_LAB + jA));
    }
    __syncthreads();
    if (w < CSIZE) {                  // warp p pushes this block's chunk to peer p
        float2 f = *reinterpret_cast<float2*>(&sOut[2 * l]);
        unsigned long long v;
        asm("mov.b64 %0, {%1,%2};" : "=l"(v) : "f"(f.x), "f"(f.y));
        st_dsmem64(smem_u32(&sAlpha[1][rank * ROWS_PER_BLK + 2 * l]), (unsigned)w, v);
    } else if (w == CSIZE) {          // warp 16: chunk max -> all peers
        float mm = fmaxf(sOut[l], sOut[l + 32]);
        #pragma unroll
        for (int o = 16; o > 0; o >>= 1) mm = fmaxf(mm, __shfl_xor_sync(0xffffffffu, mm, o));
        mm = __shfl_sync(0xffffffffu, mm, 0);
        if (l < CSIZE)
            st_dsmem32(smem_u32(&sMaxArr[1][rank]), (unsigned)l, mm);
    }
    CLUSTER_SYNC();

    double csum = 0.0;

    for (int t = 1; t < T_LEN; ++t) {
        const int buf = t & 1, nbuf = buf ^ 1;

        // ---- global max from the 16 pushed chunk maxima: barrier-free, exact
        // (order-independent -> identical on every CTA -> deterministic).
        const float* ma = sMaxArr[buf];
        float m = fmaxf(fmaxf(fmaxf(ma[0], ma[1]),  fmaxf(ma[2], ma[3])),
                        fmaxf(fmaxf(ma[4], ma[5]),  fmaxf(ma[6], ma[7])));
        m = fmaxf(m, fmaxf(fmaxf(fmaxf(ma[8], ma[9]),   fmaxf(ma[10], ma[11])),
                           fmaxf(fmaxf(ma[12], ma[13]), fmaxf(ma[14], ma[15]))));
        if (rank == 0 && tid == 0) csum += (double)m;

        // e[i] = 2^(alpha[i]-m) <= 1  -> fp16 accumulation cannot overflow
        sEh[tid] = __float2half_rn(ex2f(sAlpha[buf][tid] - m));
        __syncthreads();

        if (l == 0 && t + 1 < T_LEN)
            fnext = __ldg(reinterpret_cast<const float2*>(pred + (size_t)(t + 1) * L_LAB + jA));

        // ---- rows jA, jA+1: s = sum_i expW[j,i]*e[i], packed half2 HFMA2 ----
        __half2 pA[4], pB[4];
        #pragma unroll
        for (int k2 = 0; k2 < 4; ++k2) {
            uint4 raw = *reinterpret_cast<const uint4*>(&sEh[k2 * 256 + 8 * l]);
            __half2 e0 = *reinterpret_cast<__half2*>(&raw.x);
            __half2 e1 = *reinterpret_cast<__half2*>(&raw.y);
            __half2 e2 = *reinterpret_cast<__half2*>(&raw.z);
            __half2 e3 = *reinterpret_cast<__half2*>(&raw.w);
            __half2 aa = __hmul2(e0, hA[k2 * 4 + 0]);
            aa = __hfma2(e1, hA[k2 * 4 + 1], aa);
            aa = __hfma2(e2, hA[k2 * 4 + 2], aa);
            aa = __hfma2(e3, hA[k2 * 4 + 3], aa);
            pA[k2] = aa;
            __half2 bb = __hmul2(e0, hB[k2 * 4 + 0]);
            bb = __hfma2(e1, hB[k2 * 4 + 1], bb);
            bb = __hfma2(e2, hB[k2 * 4 + 2], bb);
            bb = __hfma2(e3, hB[k2 * 4 + 3], bb);
            pB[k2] = bb;
        }
        __half2 hsA = __hadd2(__hadd2(pA[0], pA[1]), __hadd2(pA[2], pA[3]));
        __half2 hsB = __hadd2(__hadd2(pB[0], pB[1]), __hadd2(pB[2], pB[3]));
        float2 fa = __half22float2(hsA);
        float2 fb = __half22float2(hsB);
        float sA = fa.x + fa.y, sB = fb.x + fb.y;
        #pragma unroll
        for (int o = 16; o > 0; o >>= 1) {
            sA += __shfl_xor_sync(0xffffffffu, sA, o);
            sB += __shfl_xor_sync(0xffffffffu, sB, o);
        }

        if (l == 0) {
            sOut[2 * w]     = lg2f_(sA) + fcur.x * LOG2E;
            sOut[2 * w + 1] = lg2f_(sB) + fcur.y * LOG2E;
            fcur = fnext;
        }
        __syncthreads();

        // ---- push data (warps 0..15) + chunk max (warp 16) to all peers ----
        if (w < CSIZE) {
            float2 f = *reinterpret_cast<float2*>(&sOut[2 * l]);
            unsigned long long vv;
            asm("mov.b64 %0, {%1,%2};" : "=l"(vv) : "f"(f.x), "f"(f.y));
            st_dsmem64(smem_u32(&sAlpha[nbuf][rank * ROWS_PER_BLK + 2 * l]), (unsigned)w, vv);
        } else if (w == CSIZE) {
            float mm = fmaxf(sOut[l], sOut[l + 32]);
            #pragma unroll
            for (int o = 16; o > 0; o >>= 1) mm = fmaxf(mm, __shfl_xor_sync(0xffffffffu, mm, o));
            mm = __shfl_sync(0xffffffffu, mm, 0);
            if (l < CSIZE)
                st_dsmem32(smem_u32(&sMaxArr[nbuf][rank]), (unsigned)l, mm);
        }
        CLUSTER_SYNC();               // orders DSMEM stores; doubles as block barrier
    }

    // alpha(T_LEN) sits in parity buffer (T_LEN & 1) == 0
    if (rank == 0) {
        g_alpha[tid] = sAlpha[0][tid];
        if (tid == 0) g_csum = csum;
    }
}

// Terminal: forward = LSE_j(alpha2(T)[j] + W2[STOP,j]) + csum, max-stabilized
// (the STOP row is uniformly -1e4; without the max everything underflows).
__global__ void crf_final(const float* __restrict__ trans, float* __restrict__ out)
{
    __shared__ float  sm[256];
    __shared__ double sd[256];
    int tid = threadIdx.x;

    float x[4];
    float m = -3.4e38f;
    #pragma unroll
    for (int q = 0; q < 4; ++q) {
        int jj = q * 256 + tid;
        float a  = g_alpha[jj];
        float wl = __ldg(&trans[(size_t)(L_LAB - 1) * L_LAB + jj]) * LOG2E;
        x[q] = a + wl;
        m = fmaxf(m, x[q]);
    }
    sm[tid] = m; __syncthreads();
    for (int s = 128; s > 0; s >>= 1) {
        if (tid < s) sm[tid] = fmaxf(sm[tid], sm[tid + s]);
        __syncthreads();
    }
    float M = sm[0];

    double loc = 0.0;
    #pragma unroll
    for (int q = 0; q < 4; ++q) loc += (double)ex2f(x[q] - M);
    sd[tid] = loc; __syncthreads();
    for (int s = 128; s > 0; s >>= 1) {
        if (tid < s) sd[tid] += sd[tid + s];
        __syncthreads();
    }
    if (tid == 0) {
        double fwd = (log2(sd[0]) + (double)M + g_csum) * LN2_D;
        out[0] = (float)(fwd - g_gold);
    }
}

extern "C" void kernel_launch(void* const* d_in, const int* in_sizes, int n_in,
                              void* d_out, int out_size)
{
    const float* pred = nullptr;
    const int*   ref  = nullptr;
    const float* trans = nullptr;
    for (int i = 0; i < n_in; ++i) {
        if (in_sizes[i] == T_LEN)                 ref   = (const int*)d_in[i];
        else if (in_sizes[i] == L_LAB * L_LAB)    trans = (const float*)d_in[i];
        else if (in_sizes[i] == T_LEN * L_LAB)    pred  = (const float*)d_in[i];
    }
    cudaFuncSetAttribute(crf_main, cudaFuncAttributeNonPortableClusterSizeAllowed, 1);

    dim3 grid(CSIZE, 2);
    crf_main<<<grid, TPB>>>(pred, ref, trans);
    crf_final<<<1, 256>>>(trans, (float*)d_out);
}